// round 3
// baseline (speedup 1.0000x reference)
#include <cuda_runtime.h>
#include <math.h>

#define Gg   64
#define Nn   1000
#define Ek   8192
#define Cc   128
#define HH   4
#define Dh   32
#define HIDd 256

// ---------------- scratch (device globals; no allocation allowed) ----------------
__device__ float g_bufA[Gg * Nn * Cc];   // 32 MB
__device__ float g_bufB[Gg * Nn * Cc];   // 32 MB
__device__ float g_dinv[Gg * Nn];
__device__ int   g_off [Gg * (Nn + 1)];
__device__ int   g_csrc[Gg * Ek];
__device__ float g_ccoef[Gg * Ek];
__device__ float g_pool[Gg * Cc];
__device__ float g_qkv [Gg * 3 * Cc];
__device__ float g_attno[Gg * Cc];
__device__ float g_xatt[Gg * Cc];
__device__ float g_hid [Gg * HIDd];
__device__ float g_nrep[Cc];

// ---------------- prep: degree, dinv, CSR-by-dst with per-edge coef ----------------
__global__ __launch_bounds__(256) void k_prep(const int* __restrict__ edge_index) {
    int gi = blockIdx.x;
    const int* src = edge_index + (size_t)gi * 2 * Ek;
    const int* dst = src + Ek;
    __shared__ int   cnt[Nn];
    __shared__ float sdinv[Nn];
    __shared__ int   soff[Nn + 1];
    __shared__ int   spart[256];
    int tid = threadIdx.x;

    for (int i = tid; i < Nn; i += 256) cnt[i] = 0;
    __syncthreads();
    for (int e = tid; e < Ek; e += 256) atomicAdd(&cnt[dst[e]], 1);
    __syncthreads();
    for (int i = tid; i < Nn; i += 256) {
        float dv = rsqrtf((float)cnt[i] + 1.0f);
        sdinv[i] = dv;
        g_dinv[gi * Nn + i] = dv;
    }
    __syncthreads();

    // exclusive scan of cnt -> soff (chunk-of-4 + Hillis-Steele on 256 partials)
    int base = tid * 4;
    int loc[4];
    int s = 0;
    #pragma unroll
    for (int j = 0; j < 4; j++) {
        int v = (base + j < Nn) ? cnt[base + j] : 0;
        loc[j] = s; s += v;
    }
    spart[tid] = s;
    __syncthreads();
    for (int d = 1; d < 256; d <<= 1) {
        int v = (tid >= d) ? spart[tid - d] : 0;
        __syncthreads();
        spart[tid] += v;
        __syncthreads();
    }
    int offb = (tid > 0) ? spart[tid - 1] : 0;
    #pragma unroll
    for (int j = 0; j < 4; j++)
        if (base + j <= Nn) soff[base + j] = offb + loc[j];
    __syncthreads();

    for (int i = tid; i <= Nn; i += 256) g_off[gi * (Nn + 1) + i] = soff[i];
    for (int i = tid; i < Nn; i += 256) cnt[i] = soff[i];   // cursors
    __syncthreads();

    for (int e = tid; e < Ek; e += 256) {
        int d_ = dst[e], s_ = src[e];
        int pos = atomicAdd(&cnt[d_], 1);
        g_csrc[gi * Ek + pos]  = s_;
        g_ccoef[gi * Ek + pos] = sdinv[s_] * sdinv[d_];
    }
}

// ---------------- GEMM: out[g] = in[g] (Nn x 128) @ W (128 x 128), packed f32x2 ----------------
// grid (16, 64), block 256, dyn smem 96 KB
__global__ __launch_bounds__(256) void k_gemm(const float* __restrict__ in,
                                              const float* __restrict__ W,
                                              float* __restrict__ out) {
    extern __shared__ float sm[];
    float* Ws = sm;               // 128*128
    float* Xs = sm + 128 * 128;   // 64*128
    int gi = blockIdx.y;
    int row0 = blockIdx.x * 64;
    const float* inp  = in  + (size_t)gi * Nn * Cc;
    float*       outp = out + (size_t)gi * Nn * Cc;
    int tid = threadIdx.x;

    // stage W (16384 floats) and X tile (64x128), vectorized
    const float4* W4 = (const float4*)W;
    float4* Ws4 = (float4*)Ws;
    for (int i = tid; i < 4096; i += 256) Ws4[i] = W4[i];
    for (int i = tid; i < 2048; i += 256) {
        int r = i >> 5, c4 = i & 31;
        int row = row0 + r;
        float4 v = make_float4(0.f, 0.f, 0.f, 0.f);
        if (row < Nn) v = ((const float4*)(inp + (size_t)row * Cc))[c4];
        ((float4*)(Xs + r * Cc))[c4] = v;
    }
    __syncthreads();

    int tx = tid & 15;   // cols tx*8 .. tx*8+7
    int ty = tid >> 4;   // rows ty*4 .. ty*4+3
    unsigned long long acc[4][4] = {};

    #pragma unroll 8
    for (int k = 0; k < 128; k++) {
        const ulonglong2* bp = (const ulonglong2*)(Ws + k * Cc + tx * 8);
        ulonglong2 B0 = bp[0], B1 = bp[1];
        unsigned long long b0 = B0.x, b1 = B0.y, b2 = B1.x, b3 = B1.y;
        #pragma unroll
        for (int r = 0; r < 4; r++) {
            float a = Xs[(ty * 4 + r) * Cc + k];
            unsigned long long ap;
            asm("mov.b64 %0, {%1, %1};" : "=l"(ap) : "f"(a));
            asm("fma.rn.f32x2 %0, %1, %2, %0;" : "+l"(acc[r][0]) : "l"(ap), "l"(b0));
            asm("fma.rn.f32x2 %0, %1, %2, %0;" : "+l"(acc[r][1]) : "l"(ap), "l"(b1));
            asm("fma.rn.f32x2 %0, %1, %2, %0;" : "+l"(acc[r][2]) : "l"(ap), "l"(b2));
            asm("fma.rn.f32x2 %0, %1, %2, %0;" : "+l"(acc[r][3]) : "l"(ap), "l"(b3));
        }
    }

    #pragma unroll
    for (int r = 0; r < 4; r++) {
        int row = row0 + ty * 4 + r;
        if (row < Nn) {
            ulonglong2* op = (ulonglong2*)(outp + (size_t)row * Cc + tx * 8);
            ulonglong2 t0; t0.x = acc[r][0]; t0.y = acc[r][1];
            ulonglong2 t1; t1.x = acc[r][2]; t1.y = acc[r][3];
            op[0] = t0; op[1] = t1;
        }
    }
}

// ---------------- aggregation: out = tanh(sum_in-edges coef*h[src] + h[n]*dinv^2 + b) ----------------
// grid (Nn, Gg), block 128
__global__ __launch_bounds__(128) void k_agg(const float* __restrict__ h,
                                             const float* __restrict__ bias,
                                             float* __restrict__ out) {
    int gi = blockIdx.y, n = blockIdx.x, f = threadIdx.x;
    const float* hp = h + (size_t)gi * Nn * Cc;
    int o0 = g_off[gi * (Nn + 1) + n];
    int o1 = g_off[gi * (Nn + 1) + n + 1];
    const int*   cs = g_csrc  + (size_t)gi * Ek;
    const float* cc = g_ccoef + (size_t)gi * Ek;

    float acc = 0.f;
    int e = o0;
    while (e < o1) {
        int m = o1 - e; if (m > 8) m = 8;
        int idx[8]; float cf[8];
        #pragma unroll
        for (int j = 0; j < 8; j++)
            if (j < m) { idx[j] = cs[e + j]; cf[j] = cc[e + j]; }
        #pragma unroll
        for (int j = 0; j < 8; j++)
            if (j < m) acc += hp[(size_t)idx[j] * Cc + f] * cf[j];
        e += m;
    }
    float dv = g_dinv[gi * Nn + n];
    float v = acc + hp[(size_t)n * Cc + f] * dv * dv + bias[f];
    out[(size_t)gi * Nn * Cc + (size_t)n * Cc + f] = tanhf(v);
}

// ---------------- pool over nodes; also zero node_repr accumulator ----------------
__global__ __launch_bounds__(128) void k_pool(const float* __restrict__ h) {
    int gi = blockIdx.x, f = threadIdx.x;
    const float* hp = h + (size_t)gi * Nn * Cc + f;
    float s0 = 0.f, s1 = 0.f, s2 = 0.f, s3 = 0.f;
    for (int n = 0; n < Nn; n += 4) {
        s0 += hp[(size_t)(n    ) * Cc];
        s1 += hp[(size_t)(n + 1) * Cc];
        s2 += hp[(size_t)(n + 2) * Cc];
        s3 += hp[(size_t)(n + 3) * Cc];
    }
    g_pool[gi * Cc + f] = (s0 + s1) + (s2 + s3);
    if (gi == 0) g_nrep[f] = 0.f;
}

// ---------------- GEMV with transposed (row-major [J,128]) matrix, warp-reduced ----------------
// vout[gi][j] = sum_k vin[gi][k] * M[j*128+k] + bias[j]
__global__ __launch_bounds__(256) void k_gemvT(const float* __restrict__ vin,
                                               const float* __restrict__ M,
                                               const float* __restrict__ bias,
                                               float* __restrict__ vout, int J) {
    int gi = blockIdx.x;
    int tid = threadIdx.x, lane = tid & 31, w = tid >> 5;  // 8 warps
    __shared__ float gs[Cc];
    if (tid < Cc) gs[tid] = vin[gi * Cc + tid];
    __syncthreads();
    float a0 = gs[lane], a1 = gs[lane + 32], a2 = gs[lane + 64], a3 = gs[lane + 96];
    for (int j = w; j < J; j += 8) {
        const float* m = M + (size_t)j * Cc;
        float p = a0 * m[lane] + a1 * m[lane + 32] + a2 * m[lane + 64] + a3 * m[lane + 96];
        #pragma unroll
        for (int o = 16; o; o >>= 1) p += __shfl_down_sync(0xffffffffu, p, o);
        if (lane == 0) vout[gi * J + j] = p + bias[j];
    }
}

// ---------------- attention: one block per head ----------------
__global__ __launch_bounds__(64) void k_attn() {
    int hh = blockIdx.x, q = threadIdx.x;   // 64 threads = 64 query graphs
    __shared__ float Q[Gg][Dh + 1];
    __shared__ float K[Gg][Dh];
    __shared__ float V[Gg][Dh];
    #pragma unroll
    for (int d = 0; d < Dh; d++) {
        Q[q][d] = g_qkv[q * 384 +           hh * Dh + d];
        K[q][d] = g_qkv[q * 384 + 128     + hh * Dh + d];
        V[q][d] = g_qkv[q * 384 + 256     + hh * Dh + d];
    }
    __syncthreads();

    float sc[Gg];
    float mx = -1e30f;
    const float scale = 0.17677669529663687f;  // 1/sqrt(32)
    #pragma unroll 4
    for (int kk = 0; kk < Gg; kk++) {
        float s = 0.f;
        #pragma unroll
        for (int d = 0; d < Dh; d++) s += Q[q][d] * K[kk][d];
        s *= scale;
        sc[kk] = s;
        mx = fmaxf(mx, s);
    }
    float sum = 0.f;
    #pragma unroll 4
    for (int kk = 0; kk < Gg; kk++) {
        float e = __expf(sc[kk] - mx);
        sc[kk] = e; sum += e;
    }
    float inv = 1.0f / sum;
    #pragma unroll
    for (int d = 0; d < Dh; d++) {
        float o = 0.f;
        #pragma unroll 4
        for (int kk = 0; kk < Gg; kk++) o += sc[kk] * V[kk][d];
        g_attno[q * Cc + hh * Dh + d] = o * inv;
    }
}

// ---------------- mlp1: hid = relu(xatt @ mw1 + mb1)  (mw1 is [128,256], coalesced) ----------------
__global__ __launch_bounds__(256) void k_mlp1(const float* __restrict__ mw1,
                                              const float* __restrict__ mb1) {
    int gi = blockIdx.x, j = threadIdx.x;  // 256
    __shared__ float xs[Cc];
    if (j < Cc) xs[j] = g_xatt[gi * Cc + j];
    __syncthreads();
    float acc = mb1[j];
    #pragma unroll 4
    for (int k = 0; k < Cc; k++) acc += xs[k] * mw1[(size_t)k * HIDd + j];
    g_hid[gi * HIDd + j] = fmaxf(acc, 0.f);
}

// ---------------- mlp2 + residual + layernorm + relu + accumulate node_repr ----------------
__global__ __launch_bounds__(128) void k_mlp2ln(const float* __restrict__ mw2,
                                                const float* __restrict__ mb2,
                                                const float* __restrict__ lng,
                                                const float* __restrict__ lnb) {
    int gi = blockIdx.x, c = threadIdx.x;  // 128
    __shared__ float hs[HIDd];
    __shared__ float red[Cc];
    hs[c]       = g_hid[gi * HIDd + c];
    hs[c + 128] = g_hid[gi * HIDd + c + 128];
    __syncthreads();
    float acc = g_xatt[gi * Cc + c] + mb2[c];
    #pragma unroll 4
    for (int k = 0; k < HIDd; k++) acc += hs[k] * mw2[(size_t)k * Cc + c];

    red[c] = acc; __syncthreads();
    for (int s = 64; s; s >>= 1) { if (c < s) red[c] += red[c + s]; __syncthreads(); }
    float mu = red[0] * (1.0f / Cc);
    __syncthreads();
    float dx = acc - mu;
    red[c] = dx * dx; __syncthreads();
    for (int s = 64; s; s >>= 1) { if (c < s) red[c] += red[c + s]; __syncthreads(); }
    float var = red[0] * (1.0f / Cc);
    float y = dx * rsqrtf(var + 1e-5f) * lng[c] + lnb[c];
    atomicAdd(&g_nrep[c], fmaxf(y, 0.f));
}

// ---------------- final logits ----------------
__global__ __launch_bounds__(128) void k_out(const float* __restrict__ lw,
                                             const float* __restrict__ lb,
                                             float* __restrict__ out) {
    int c = threadIdx.x;  // 128
    __shared__ float s0[Cc], s1[Cc];
    float v = g_nrep[c];
    s0[c] = v * lw[c * 2 + 0];
    s1[c] = v * lw[c * 2 + 1];
    __syncthreads();
    for (int s = 64; s; s >>= 1) {
        if (c < s) { s0[c] += s0[c + s]; s1[c] += s1[c + s]; }
        __syncthreads();
    }
    if (c == 0) { out[0] = s0[0] + lb[0]; out[1] = s1[0] + lb[1]; }
}

// ---------------- launch ----------------
extern "C" void kernel_launch(void* const* d_in, const int* in_sizes, int n_in,
                              void* d_out, int out_size) {
    const float* x     = (const float*)d_in[0];
    const int*   ei    = (const int*)  d_in[1];
    const float* W0    = (const float*)d_in[2];
    const float* b0    = (const float*)d_in[3];
    const float* W1    = (const float*)d_in[4];
    const float* b1    = (const float*)d_in[5];
    const float* in_w  = (const float*)d_in[6];
    const float* in_b  = (const float*)d_in[7];
    const float* out_w = (const float*)d_in[8];
    const float* out_b = (const float*)d_in[9];
    const float* ln2_g = (const float*)d_in[10];
    const float* ln2_b = (const float*)d_in[11];
    const float* mw1   = (const float*)d_in[12];
    const float* mb1   = (const float*)d_in[13];
    const float* mw2   = (const float*)d_in[14];
    const float* mb2   = (const float*)d_in[15];
    const float* lw    = (const float*)d_in[16];
    const float* lb    = (const float*)d_in[17];
    float* out = (float*)d_out;

    void *pA, *pB, *pPool, *pQkv, *pAttno, *pXatt;
    cudaGetSymbolAddress(&pA, g_bufA);
    cudaGetSymbolAddress(&pB, g_bufB);
    cudaGetSymbolAddress(&pPool, g_pool);
    cudaGetSymbolAddress(&pQkv, g_qkv);
    cudaGetSymbolAddress(&pAttno, g_attno);
    cudaGetSymbolAddress(&pXatt, g_xatt);
    float* A = (float*)pA;
    float* B = (float*)pB;

    cudaFuncSetAttribute(k_gemm, cudaFuncAttributeMaxDynamicSharedMemorySize, 96 * 1024);

    k_prep<<<Gg, 256>>>(ei);
    k_gemm<<<dim3(16, Gg), 256, 96 * 1024>>>(x, W0, A);
    k_agg <<<dim3(Nn, Gg), 128>>>(A, b0, B);
    k_gemm<<<dim3(16, Gg), 256, 96 * 1024>>>(B, W1, A);
    k_agg <<<dim3(Nn, Gg), 128>>>(A, b1, B);
    k_pool<<<Gg, 128>>>(B);
    k_gemvT<<<Gg, 256>>>((const float*)pPool, in_w, in_b, (float*)pQkv, 3 * Cc);
    k_attn<<<HH, 64>>>();
    k_gemvT<<<Gg, 256>>>((const float*)pAttno, out_w, out_b, (float*)pXatt, Cc);
    k_mlp1<<<Gg, 256>>>(mw1, mb1);
    k_mlp2ln<<<Gg, 128>>>(mw2, mb2, ln2_g, ln2_b);
    k_out<<<1, 128>>>(lw, lb, out);
}

// round 5
// speedup vs baseline: 1.0103x; 1.0103x over previous
#include <cuda_runtime.h>
#include <math.h>

#define Gg   64
#define Nn   1000
#define Ek   8192
#define Cc   128
#define HH   4
#define Dh   32
#define HIDd 256

// ---------------- scratch (device globals; no allocation allowed) ----------------
__device__ float g_bufA[Gg * Nn * Cc];   // 32 MB
__device__ float g_bufB[Gg * Nn * Cc];   // 32 MB
__device__ float g_dinv[Gg * Nn];
__device__ int   g_off [Gg * (Nn + 1)];
__device__ int   g_csrc[Gg * Ek];
__device__ float g_ccoef[Gg * Ek];
__device__ float g_pool[Gg * Cc];
__device__ float g_qkv [Gg * 3 * Cc];
__device__ float g_attno[Gg * Cc];
__device__ float g_xatt[Gg * Cc];
__device__ float g_hid [Gg * HIDd];
__device__ float g_nrep[Cc];

// ---------------- prep: degree, dinv, CSR-by-dst with per-edge coef ----------------
__global__ __launch_bounds__(256) void k_prep(const int* __restrict__ edge_index) {
    int gi = blockIdx.x;
    const int* src = edge_index + (size_t)gi * 2 * Ek;
    const int* dst = src + Ek;
    __shared__ int   cnt[Nn];
    __shared__ float sdinv[Nn];
    __shared__ int   soff[Nn + 1];
    __shared__ int   spart[256];
    int tid = threadIdx.x;

    for (int i = tid; i < Nn; i += 256) cnt[i] = 0;
    __syncthreads();
    for (int e = tid; e < Ek; e += 256) atomicAdd(&cnt[dst[e]], 1);
    __syncthreads();
    for (int i = tid; i < Nn; i += 256) {
        float dv = rsqrtf((float)cnt[i] + 1.0f);
        sdinv[i] = dv;
        g_dinv[gi * Nn + i] = dv;
    }
    __syncthreads();

    // exclusive scan of cnt -> soff (chunk-of-4 + Hillis-Steele on 256 partials)
    int base = tid * 4;
    int loc[4];
    int s = 0;
    #pragma unroll
    for (int j = 0; j < 4; j++) {
        int v = (base + j < Nn) ? cnt[base + j] : 0;
        loc[j] = s; s += v;
    }
    spart[tid] = s;
    __syncthreads();
    for (int d = 1; d < 256; d <<= 1) {
        int v = (tid >= d) ? spart[tid - d] : 0;
        __syncthreads();
        spart[tid] += v;
        __syncthreads();
    }
    int offb = (tid > 0) ? spart[tid - 1] : 0;
    #pragma unroll
    for (int j = 0; j < 4; j++)
        if (base + j <= Nn) soff[base + j] = offb + loc[j];
    __syncthreads();

    for (int i = tid; i <= Nn; i += 256) g_off[gi * (Nn + 1) + i] = soff[i];
    for (int i = tid; i < Nn; i += 256) cnt[i] = soff[i];   // cursors
    __syncthreads();

    for (int e = tid; e < Ek; e += 256) {
        int d_ = dst[e], s_ = src[e];
        int pos = atomicAdd(&cnt[d_], 1);
        g_csrc[gi * Ek + pos]  = s_;
        g_ccoef[gi * Ek + pos] = sdinv[s_] * sdinv[d_];
    }
}

// ---------------- GEMM: out[g] = in[g] (Nn x 128) @ W (128 x 128), packed f32x2 ----------------
// grid (16, 64), block 256, dyn smem 96 KB
__global__ __launch_bounds__(256) void k_gemm(const float* __restrict__ in,
                                              const float* __restrict__ W,
                                              float* __restrict__ out) {
    extern __shared__ float sm[];
    float* Ws = sm;               // 128*128
    float* Xs = sm + 128 * 128;   // 64*128
    int gi = blockIdx.y;
    int row0 = blockIdx.x * 64;
    const float* inp  = in  + (size_t)gi * Nn * Cc;
    float*       outp = out + (size_t)gi * Nn * Cc;
    int tid = threadIdx.x;

    // stage W (16384 floats) and X tile (64x128), vectorized
    const float4* W4 = (const float4*)W;
    float4* Ws4 = (float4*)Ws;
    for (int i = tid; i < 4096; i += 256) Ws4[i] = W4[i];
    for (int i = tid; i < 2048; i += 256) {
        int r = i >> 5, c4 = i & 31;
        int row = row0 + r;
        float4 v = make_float4(0.f, 0.f, 0.f, 0.f);
        if (row < Nn) v = ((const float4*)(inp + (size_t)row * Cc))[c4];
        ((float4*)(Xs + r * Cc))[c4] = v;
    }
    __syncthreads();

    int tx = tid & 15;   // cols tx*8 .. tx*8+7
    int ty = tid >> 4;   // rows ty*4 .. ty*4+3
    unsigned long long acc[4][4] = {};

    #pragma unroll 8
    for (int k = 0; k < 128; k++) {
        const ulonglong2* bp = (const ulonglong2*)(Ws + k * Cc + tx * 8);
        ulonglong2 B0 = bp[0], B1 = bp[1];
        unsigned long long b0 = B0.x, b1 = B0.y, b2 = B1.x, b3 = B1.y;
        #pragma unroll
        for (int r = 0; r < 4; r++) {
            float a = Xs[(ty * 4 + r) * Cc + k];
            unsigned long long ap;
            asm("mov.b64 %0, {%1, %1};" : "=l"(ap) : "f"(a));
            asm("fma.rn.f32x2 %0, %1, %2, %0;" : "+l"(acc[r][0]) : "l"(ap), "l"(b0));
            asm("fma.rn.f32x2 %0, %1, %2, %0;" : "+l"(acc[r][1]) : "l"(ap), "l"(b1));
            asm("fma.rn.f32x2 %0, %1, %2, %0;" : "+l"(acc[r][2]) : "l"(ap), "l"(b2));
            asm("fma.rn.f32x2 %0, %1, %2, %0;" : "+l"(acc[r][3]) : "l"(ap), "l"(b3));
        }
    }

    #pragma unroll
    for (int r = 0; r < 4; r++) {
        int row = row0 + ty * 4 + r;
        if (row < Nn) {
            ulonglong2* op = (ulonglong2*)(outp + (size_t)row * Cc + tx * 8);
            ulonglong2 t0; t0.x = acc[r][0]; t0.y = acc[r][1];
            ulonglong2 t1; t1.x = acc[r][2]; t1.y = acc[r][3];
            op[0] = t0; op[1] = t1;
        }
    }
}

// ---------------- aggregation: out = tanh(sum_in-edges coef*h[src] + h[n]*dinv^2 + b) ----------------
// grid (Nn, Gg), block 128
__global__ __launch_bounds__(128) void k_agg(const float* __restrict__ h,
                                             const float* __restrict__ bias,
                                             float* __restrict__ out) {
    int gi = blockIdx.y, n = blockIdx.x, f = threadIdx.x;
    const float* hp = h + (size_t)gi * Nn * Cc;
    int o0 = g_off[gi * (Nn + 1) + n];
    int o1 = g_off[gi * (Nn + 1) + n + 1];
    const int*   cs = g_csrc  + (size_t)gi * Ek;
    const float* cc = g_ccoef + (size_t)gi * Ek;

    float acc = 0.f;
    int e = o0;
    while (e < o1) {
        int m = o1 - e; if (m > 8) m = 8;
        int idx[8]; float cf[8];
        #pragma unroll
        for (int j = 0; j < 8; j++)
            if (j < m) { idx[j] = cs[e + j]; cf[j] = cc[e + j]; }
        #pragma unroll
        for (int j = 0; j < 8; j++)
            if (j < m) acc += hp[(size_t)idx[j] * Cc + f] * cf[j];
        e += m;
    }
    float dv = g_dinv[gi * Nn + n];
    float v = acc + hp[(size_t)n * Cc + f] * dv * dv + bias[f];
    out[(size_t)gi * Nn * Cc + (size_t)n * Cc + f] = tanhf(v);
}

// ---------------- pool over nodes; also zero node_repr accumulator ----------------
__global__ __launch_bounds__(128) void k_pool(const float* __restrict__ h) {
    int gi = blockIdx.x, f = threadIdx.x;
    const float* hp = h + (size_t)gi * Nn * Cc + f;
    float s0 = 0.f, s1 = 0.f, s2 = 0.f, s3 = 0.f;
    for (int n = 0; n < Nn; n += 4) {
        s0 += hp[(size_t)(n    ) * Cc];
        s1 += hp[(size_t)(n + 1) * Cc];
        s2 += hp[(size_t)(n + 2) * Cc];
        s3 += hp[(size_t)(n + 3) * Cc];
    }
    g_pool[gi * Cc + f] = (s0 + s1) + (s2 + s3);
    if (gi == 0) g_nrep[f] = 0.f;
}

// ---------------- GEMV with transposed (row-major [J,128]) matrix, warp-reduced ----------------
// vout[gi][j] = sum_k vin[gi][k] * M[j*128+k] + bias[j]
__global__ __launch_bounds__(256) void k_gemvT(const float* __restrict__ vin,
                                               const float* __restrict__ M,
                                               const float* __restrict__ bias,
                                               float* __restrict__ vout, int J) {
    int gi = blockIdx.x;
    int tid = threadIdx.x, lane = tid & 31, w = tid >> 5;  // 8 warps
    __shared__ float gs[Cc];
    if (tid < Cc) gs[tid] = vin[gi * Cc + tid];
    __syncthreads();
    float a0 = gs[lane], a1 = gs[lane + 32], a2 = gs[lane + 64], a3 = gs[lane + 96];
    for (int j = w; j < J; j += 8) {
        const float* m = M + (size_t)j * Cc;
        float p = a0 * m[lane] + a1 * m[lane + 32] + a2 * m[lane + 64] + a3 * m[lane + 96];
        #pragma unroll
        for (int o = 16; o; o >>= 1) p += __shfl_down_sync(0xffffffffu, p, o);
        if (lane == 0) vout[gi * J + j] = p + bias[j];
    }
}

// ---------------- attention: one block per head ----------------
__global__ __launch_bounds__(64) void k_attn() {
    int hh = blockIdx.x, q = threadIdx.x;   // 64 threads = 64 query graphs
    __shared__ float Q[Gg][Dh + 1];
    __shared__ float K[Gg][Dh];
    __shared__ float V[Gg][Dh];
    #pragma unroll
    for (int d = 0; d < Dh; d++) {
        Q[q][d] = g_qkv[q * 384 +           hh * Dh + d];
        K[q][d] = g_qkv[q * 384 + 128     + hh * Dh + d];
        V[q][d] = g_qkv[q * 384 + 256     + hh * Dh + d];
    }
    __syncthreads();

    float sc[Gg];
    float mx = -1e30f;
    const float scale = 0.17677669529663687f;  // 1/sqrt(32)
    #pragma unroll 4
    for (int kk = 0; kk < Gg; kk++) {
        float s = 0.f;
        #pragma unroll
        for (int d = 0; d < Dh; d++) s += Q[q][d] * K[kk][d];
        s *= scale;
        sc[kk] = s;
        mx = fmaxf(mx, s);
    }
    float sum = 0.f;
    #pragma unroll 4
    for (int kk = 0; kk < Gg; kk++) {
        float e = __expf(sc[kk] - mx);
        sc[kk] = e; sum += e;
    }
    float inv = 1.0f / sum;
    #pragma unroll
    for (int d = 0; d < Dh; d++) {
        float o = 0.f;
        #pragma unroll 4
        for (int kk = 0; kk < Gg; kk++) o += sc[kk] * V[kk][d];
        g_attno[q * Cc + hh * Dh + d] = o * inv;
    }
}

// ---------------- mlp1: hid = relu(xatt @ mw1 + mb1)  (mw1 is [128,256], coalesced) ----------------
__global__ __launch_bounds__(256) void k_mlp1(const float* __restrict__ mw1,
                                              const float* __restrict__ mb1) {
    int gi = blockIdx.x, j = threadIdx.x;  // 256
    __shared__ float xs[Cc];
    if (j < Cc) xs[j] = g_xatt[gi * Cc + j];
    __syncthreads();
    float acc = mb1[j];
    #pragma unroll 4
    for (int k = 0; k < Cc; k++) acc += xs[k] * mw1[(size_t)k * HIDd + j];
    g_hid[gi * HIDd + j] = fmaxf(acc, 0.f);
}

// ---------------- mlp2 + residual + layernorm + relu + accumulate node_repr ----------------
__global__ __launch_bounds__(128) void k_mlp2ln(const float* __restrict__ mw2,
                                                const float* __restrict__ mb2,
                                                const float* __restrict__ lng,
                                                const float* __restrict__ lnb) {
    int gi = blockIdx.x, c = threadIdx.x;  // 128
    __shared__ float hs[HIDd];
    __shared__ float red[Cc];
    hs[c]       = g_hid[gi * HIDd + c];
    hs[c + 128] = g_hid[gi * HIDd + c + 128];
    __syncthreads();
    float acc = g_xatt[gi * Cc + c] + mb2[c];
    #pragma unroll 4
    for (int k = 0; k < HIDd; k++) acc += hs[k] * mw2[(size_t)k * Cc + c];

    red[c] = acc; __syncthreads();
    for (int s = 64; s; s >>= 1) { if (c < s) red[c] += red[c + s]; __syncthreads(); }
    float mu = red[0] * (1.0f / Cc);
    __syncthreads();
    float dx = acc - mu;
    red[c] = dx * dx; __syncthreads();
    for (int s = 64; s; s >>= 1) { if (c < s) red[c] += red[c + s]; __syncthreads(); }
    float var = red[0] * (1.0f / Cc);
    float y = dx * rsqrtf(var + 1e-5f) * lng[c] + lnb[c];
    atomicAdd(&g_nrep[c], fmaxf(y, 0.f));
}

// ---------------- final logits ----------------
__global__ __launch_bounds__(128) void k_out(const float* __restrict__ lw,
                                             const float* __restrict__ lb,
                                             float* __restrict__ out) {
    int c = threadIdx.x;  // 128
    __shared__ float s0[Cc], s1[Cc];
    float v = g_nrep[c];
    s0[c] = v * lw[c * 2 + 0];
    s1[c] = v * lw[c * 2 + 1];
    __syncthreads();
    for (int s = 64; s; s >>= 1) {
        if (c < s) { s0[c] += s0[c + s]; s1[c] += s1[c + s]; }
        __syncthreads();
    }
    if (c == 0) { out[0] = s0[0] + lb[0]; out[1] = s1[0] + lb[1]; }
}

// ---------------- launch ----------------
extern "C" void kernel_launch(void* const* d_in, const int* in_sizes, int n_in,
                              void* d_out, int out_size) {
    const float* x     = (const float*)d_in[0];
    const int*   ei    = (const int*)  d_in[1];
    const float* W0    = (const float*)d_in[2];
    const float* b0    = (const float*)d_in[3];
    const float* W1    = (const float*)d_in[4];
    const float* b1    = (const float*)d_in[5];
    const float* in_w  = (const float*)d_in[6];
    const float* in_b  = (const float*)d_in[7];
    const float* out_w = (const float*)d_in[8];
    const float* out_b = (const float*)d_in[9];
    const float* ln2_g = (const float*)d_in[10];
    const float* ln2_b = (const float*)d_in[11];
    const float* mw1   = (const float*)d_in[12];
    const float* mb1   = (const float*)d_in[13];
    const float* mw2   = (const float*)d_in[14];
    const float* mb2   = (const float*)d_in[15];
    const float* lw    = (const float*)d_in[16];
    const float* lb    = (const float*)d_in[17];
    float* out = (float*)d_out;

    void *pA, *pB, *pPool, *pQkv, *pAttno, *pXatt;
    cudaGetSymbolAddress(&pA, g_bufA);
    cudaGetSymbolAddress(&pB, g_bufB);
    cudaGetSymbolAddress(&pPool, g_pool);
    cudaGetSymbolAddress(&pQkv, g_qkv);
    cudaGetSymbolAddress(&pAttno, g_attno);
    cudaGetSymbolAddress(&pXatt, g_xatt);
    float* A = (float*)pA;
    float* B = (float*)pB;

    cudaFuncSetAttribute(k_gemm, cudaFuncAttributeMaxDynamicSharedMemorySize, 96 * 1024);

    k_prep<<<Gg, 256>>>(ei);
    k_gemm<<<dim3(16, Gg), 256, 96 * 1024>>>(x, W0, A);
    k_agg <<<dim3(Nn, Gg), 128>>>(A, b0, B);
    k_gemm<<<dim3(16, Gg), 256, 96 * 1024>>>(B, W1, A);
    k_agg <<<dim3(Nn, Gg), 128>>>(A, b1, B);
    k_pool<<<Gg, 128>>>(B);
    k_gemvT<<<Gg, 256>>>((const float*)pPool, in_w, in_b, (float*)pQkv, 3 * Cc);
    k_attn<<<HH, 64>>>();
    k_gemvT<<<Gg, 256>>>((const float*)pAttno, out_w, out_b, (float*)pXatt, Cc);
    k_mlp1<<<Gg, 256>>>(mw1, mb1);
    k_mlp2ln<<<Gg, 128>>>(mw2, mb2, ln2_g, ln2_b);
    k_out<<<1, 128>>>(lw, lb, out);
}